// round 16
// baseline (speedup 1.0000x reference)
#include <cuda_runtime.h>
#include <cuda_bf16.h>
#include <math.h>

// Problem constants (fixed by reference setup_inputs)
#define NQ      65536
#define EMBED   1024
#define NPROTO  512
#define HID     128

// Scratch (device globals -- no allocation allowed)
__device__ int   g_idx[NQ];
__device__ float g_pp[NPROTO * HID];   // b1 + prototypes @ W1[1024:2048]

// ---------------------------------------------------------------------------
// f32x2 packed helpers (sm_100+ PTX)
// ---------------------------------------------------------------------------
__device__ __forceinline__ unsigned long long pack2(float lo, float hi) {
    unsigned long long r;
    asm("mov.b64 %0, {%1, %2};" : "=l"(r) : "f"(lo), "f"(hi));
    return r;
}
__device__ __forceinline__ unsigned long long fma2(unsigned long long a,
                                                   unsigned long long b,
                                                   unsigned long long c) {
    unsigned long long d;
    asm("fma.rn.f32x2 %0, %1, %2, %3;" : "=l"(d) : "l"(a), "l"(b), "l"(c));
    return d;
}
__device__ __forceinline__ void unpack2(float& lo, float& hi, unsigned long long v) {
    asm("mov.b64 {%0, %1}, %2;" : "=f"(lo), "=f"(hi) : "l"(v));
}

// ---------------------------------------------------------------------------
// Kernel 1: proto projection  pp[p][h] = b1[h] + sum_k proto[p][k] * W1[1024+k][h]
// 64 blocks x 256 threads, 8 prototypes per block.
// ---------------------------------------------------------------------------
__global__ void __launch_bounds__(256) proto_proj_kernel(
    const float* __restrict__ protos,
    const float* __restrict__ W1,
    const float* __restrict__ b1)
{
    __shared__ float sp[8][EMBED];   // 32 KB

    int pbase = blockIdx.x * 8;
    // cooperative load: 8*1024 floats = 2048 float4
    const float4* src = (const float4*)(protos + (size_t)pbase * EMBED);
    float4* dst = (float4*)&sp[0][0];
    for (int i = threadIdx.x; i < 8 * EMBED / 4; i += 256)
        dst[i] = src[i];
    __syncthreads();

    int h  = threadIdx.x & 127;          // hidden index
    int pl = (threadIdx.x >> 7) * 4;     // 0 or 4 : 4 local protos per thread

    float a0 = 0.f, a1 = 0.f, a2 = 0.f, a3 = 0.f;
    const float* w = W1 + (size_t)EMBED * HID + h;   // bottom half, column h
    #pragma unroll 4
    for (int k = 0; k < EMBED; k++) {
        float wv = w[(size_t)k * HID];
        a0 = fmaf(sp[pl + 0][k], wv, a0);
        a1 = fmaf(sp[pl + 1][k], wv, a1);
        a2 = fmaf(sp[pl + 2][k], wv, a2);
        a3 = fmaf(sp[pl + 3][k], wv, a3);
    }
    float bb = b1[h];
    g_pp[(pbase + pl + 0) * HID + h] = a0 + bb;
    g_pp[(pbase + pl + 1) * HID + h] = a1 + bb;
    g_pp[(pbase + pl + 2) * HID + h] = a2 + bb;
    g_pp[(pbase + pl + 3) * HID + h] = a3 + bb;
}

// ---------------------------------------------------------------------------
// Kernel 2: per-row argmin over 512 distances. One warp per query row.
// Tie-break to lowest index (matches jnp.argmin semantics).
// ---------------------------------------------------------------------------
__global__ void __launch_bounds__(256) argmin_kernel(const float* __restrict__ dist)
{
    int gwarp = (blockIdx.x * blockDim.x + threadIdx.x) >> 5;
    int lane  = threadIdx.x & 31;
    if (gwarp >= NQ) return;

    const float4* row = (const float4*)(dist + (size_t)gwarp * NPROTO);

    float best = __int_as_float(0x7f800000);   // +inf
    int   bi   = 0x7fffffff;
    #pragma unroll
    for (int j = 0; j < 4; j++) {
        int f4 = lane + 32 * j;                // ascending per lane -> earliest kept via strict <
        float4 v = row[f4];
        int base = f4 * 4;
        if (v.x < best) { best = v.x; bi = base;     }
        if (v.y < best) { best = v.y; bi = base + 1; }
        if (v.z < best) { best = v.z; bi = base + 2; }
        if (v.w < best) { best = v.w; bi = base + 3; }
    }
    #pragma unroll
    for (int off = 16; off; off >>= 1) {
        float ob = __shfl_down_sync(0xffffffffu, best, off);
        int   oi = __shfl_down_sync(0xffffffffu, bi,   off);
        if (ob < best || (ob == best && oi < bi)) { best = ob; bi = oi; }
    }
    if (lane == 0) g_idx[gwarp] = bi;
}

// ---------------------------------------------------------------------------
// Kernel 3: fused GEMM + epilogue.
//   h[m, :] = relu( qf[m, :] @ W1_top + g_pp[g_idx[m], :] )
//   out[m]  = sigmoid( h[m, :] @ W2 + b2 )
// Tile: BM=128, BN=128(full), BK=16. 256 threads (16x16), 8x8 microtile,
// accumulators as f32x2 pairs along N. A stored splatted in smem.
// ---------------------------------------------------------------------------
__global__ void __launch_bounds__(256, 2) mlp_kernel(
    const float* __restrict__ qf,
    const float* __restrict__ W1,
    const float* __restrict__ W2,
    const float* __restrict__ b2,
    float* __restrict__ out)
{
    __shared__ unsigned long long As[16][132];  // splatted (v,v) pairs, k-major; 16.5 KB
    __shared__ float Bs[16][128];               // 8 KB

    const int tid = threadIdx.x;
    const int tx  = tid & 15;    // N group (8 cols each)
    const int ty  = tid >> 4;    // M group (8 rows each)
    const int m0  = blockIdx.x * 128;

    unsigned long long acc[8][4];
    #pragma unroll
    for (int r = 0; r < 8; r++)
        #pragma unroll
        for (int c = 0; c < 4; c++) acc[r][c] = 0ull;   // (0.0f, 0.0f)

    // A load mapping: thread -> row arow, 8 consecutive k starting at kbase
    const int arow  = tid >> 1;
    const int kbase = (tid & 1) * 8;
    const float* aptr = qf + (size_t)(m0 + arow) * EMBED + kbase;

    // B load mapping: thread -> (row brow & brow+8, 4 cols at bcol)
    const int brow = tid >> 5;          // 0..7
    const int bcol = (tid & 31) * 4;
    const float* bptr = W1 + (size_t)brow * HID + bcol;

    for (int kt = 0; kt < EMBED / 16; kt++) {
        const int k0 = kt * 16;

        float4 av0 = *(const float4*)(aptr + k0);
        float4 av1 = *(const float4*)(aptr + k0 + 4);
        float4 bv0 = *(const float4*)(bptr + (size_t)k0 * HID);
        float4 bv1 = *(const float4*)(bptr + (size_t)(k0 + 8) * HID);

        As[kbase + 0][arow] = pack2(av0.x, av0.x);
        As[kbase + 1][arow] = pack2(av0.y, av0.y);
        As[kbase + 2][arow] = pack2(av0.z, av0.z);
        As[kbase + 3][arow] = pack2(av0.w, av0.w);
        As[kbase + 4][arow] = pack2(av1.x, av1.x);
        As[kbase + 5][arow] = pack2(av1.y, av1.y);
        As[kbase + 6][arow] = pack2(av1.z, av1.z);
        As[kbase + 7][arow] = pack2(av1.w, av1.w);

        *(float4*)&Bs[brow][bcol]     = bv0;
        *(float4*)&Bs[brow + 8][bcol] = bv1;
        __syncthreads();

        #pragma unroll
        for (int k = 0; k < 16; k++) {
            ulonglong2 a01 = *(const ulonglong2*)&As[k][ty * 8 + 0];
            ulonglong2 a23 = *(const ulonglong2*)&As[k][ty * 8 + 2];
            ulonglong2 a45 = *(const ulonglong2*)&As[k][ty * 8 + 4];
            ulonglong2 a67 = *(const ulonglong2*)&As[k][ty * 8 + 6];
            ulonglong2 b01 = *(const ulonglong2*)&Bs[k][tx * 8 + 0];
            ulonglong2 b23 = *(const ulonglong2*)&Bs[k][tx * 8 + 4];

            acc[0][0] = fma2(a01.x, b01.x, acc[0][0]);
            acc[0][1] = fma2(a01.x, b01.y, acc[0][1]);
            acc[0][2] = fma2(a01.x, b23.x, acc[0][2]);
            acc[0][3] = fma2(a01.x, b23.y, acc[0][3]);
            acc[1][0] = fma2(a01.y, b01.x, acc[1][0]);
            acc[1][1] = fma2(a01.y, b01.y, acc[1][1]);
            acc[1][2] = fma2(a01.y, b23.x, acc[1][2]);
            acc[1][3] = fma2(a01.y, b23.y, acc[1][3]);
            acc[2][0] = fma2(a23.x, b01.x, acc[2][0]);
            acc[2][1] = fma2(a23.x, b01.y, acc[2][1]);
            acc[2][2] = fma2(a23.x, b23.x, acc[2][2]);
            acc[2][3] = fma2(a23.x, b23.y, acc[2][3]);
            acc[3][0] = fma2(a23.y, b01.x, acc[3][0]);
            acc[3][1] = fma2(a23.y, b01.y, acc[3][1]);
            acc[3][2] = fma2(a23.y, b23.x, acc[3][2]);
            acc[3][3] = fma2(a23.y, b23.y, acc[3][3]);
            acc[4][0] = fma2(a45.x, b01.x, acc[4][0]);
            acc[4][1] = fma2(a45.x, b01.y, acc[4][1]);
            acc[4][2] = fma2(a45.x, b23.x, acc[4][2]);
            acc[4][3] = fma2(a45.x, b23.y, acc[4][3]);
            acc[5][0] = fma2(a45.y, b01.x, acc[5][0]);
            acc[5][1] = fma2(a45.y, b01.y, acc[5][1]);
            acc[5][2] = fma2(a45.y, b23.x, acc[5][2]);
            acc[5][3] = fma2(a45.y, b23.y, acc[5][3]);
            acc[6][0] = fma2(a67.x, b01.x, acc[6][0]);
            acc[6][1] = fma2(a67.x, b01.y, acc[6][1]);
            acc[6][2] = fma2(a67.x, b23.x, acc[6][2]);
            acc[6][3] = fma2(a67.x, b23.y, acc[6][3]);
            acc[7][0] = fma2(a67.y, b01.x, acc[7][0]);
            acc[7][1] = fma2(a67.y, b01.y, acc[7][1]);
            acc[7][2] = fma2(a67.y, b23.x, acc[7][2]);
            acc[7][3] = fma2(a67.y, b23.y, acc[7][3]);
        }
        __syncthreads();
    }

    // ---- fused epilogue: +pp[idx] (b1 folded), relu, dot with W2, sigmoid ----
    float w2v[8];
    #pragma unroll
    for (int c = 0; c < 8; c++) w2v[c] = W2[tx * 8 + c];
    const float bias2 = b2[0];

    #pragma unroll
    for (int r = 0; r < 8; r++) {
        const int m = m0 + ty * 8 + r;
        const int pidx = g_idx[m];
        const float* pp = g_pp + (size_t)pidx * HID + tx * 8;
        float4 p0 = *(const float4*)(pp);
        float4 p1 = *(const float4*)(pp + 4);
        float pa[8] = {p0.x, p0.y, p0.z, p0.w, p1.x, p1.y, p1.z, p1.w};

        float s = 0.f;
        #pragma unroll
        for (int c = 0; c < 4; c++) {
            float h0, h1;
            unpack2(h0, h1, acc[r][c]);
            float v0 = h0 + pa[2 * c];
            float v1 = h1 + pa[2 * c + 1];
            v0 = v0 > 0.f ? v0 : 0.f;
            v1 = v1 > 0.f ? v1 : 0.f;
            s = fmaf(v0, w2v[2 * c], s);
            s = fmaf(v1, w2v[2 * c + 1], s);
        }
        // reduce across the 16 tx lanes (same warp, width-16 segments)
        #pragma unroll
        for (int off = 8; off; off >>= 1)
            s += __shfl_down_sync(0xffffffffu, s, off, 16);

        if (tx == 0)
            out[m] = 1.0f / (1.0f + expf(-(s + bias2)));
    }
}

// ---------------------------------------------------------------------------
// Launch: proto_proj and argmin are independent; mlp consumes both.
// All plain launches on the capture stream; no allocs, no syncs.
// ---------------------------------------------------------------------------
extern "C" void kernel_launch(void* const* d_in, const int* in_sizes, int n_in,
                              void* d_out, int out_size)
{
    const float* qf     = (const float*)d_in[0];   // [65536,1024]
    const float* protos = (const float*)d_in[1];   // [512,1024]
    const float* dist   = (const float*)d_in[2];   // [65536,512]
    const float* W1     = (const float*)d_in[3];   // [2048,128]
    const float* b1     = (const float*)d_in[4];   // [128]
    const float* W2     = (const float*)d_in[5];   // [128]  (shape [128,1])
    const float* b2     = (const float*)d_in[6];   // [1]
    float* out = (float*)d_out;                    // [65536]

    proto_proj_kernel<<<NPROTO / 8, 256>>>(protos, W1, b1);
    argmin_kernel<<<(NQ * 32) / 256, 256>>>(dist);
    mlp_kernel<<<NQ / 128, 256>>>(qf, W1, W2, b2, out);
}

// round 17
// speedup vs baseline: 1.6425x; 1.6425x over previous
#include <cuda_runtime.h>
#include <cuda_bf16.h>
#include <math.h>

// Problem constants (fixed by reference setup_inputs)
#define NQ      65536
#define EMBED   1024
#define NPROTO  512
#define HID     128

// Scratch (device globals -- no allocation allowed)
__device__ int   g_idx[NQ];
__device__ float g_pp[NPROTO * HID];   // b1 + prototypes @ W1[1024:2048]

// ---------------------------------------------------------------------------
// f32x2 packed helpers (sm_100+ PTX)
// ---------------------------------------------------------------------------
__device__ __forceinline__ unsigned long long pack2(float lo, float hi) {
    unsigned long long r;
    asm("mov.b64 %0, {%1, %2};" : "=l"(r) : "f"(lo), "f"(hi));
    return r;
}
__device__ __forceinline__ unsigned long long fma2(unsigned long long a,
                                                   unsigned long long b,
                                                   unsigned long long c) {
    unsigned long long d;
    asm("fma.rn.f32x2 %0, %1, %2, %3;" : "=l"(d) : "l"(a), "l"(b), "l"(c));
    return d;
}
__device__ __forceinline__ void unpack2(float& lo, float& hi, unsigned long long v) {
    asm("mov.b64 {%0, %1}, %2;" : "=f"(lo), "=f"(hi) : "l"(v));
}

// ---------------------------------------------------------------------------
// Kernel 1: proto projection  pp[p][h] = b1[h] + sum_k proto[p][k] * W1[1024+k][h]
// 128 blocks x 128 threads, 4 prototypes per block, 8-wide unrolled K loop.
// W1 bottom half (512 KB) is L2-resident after the first wave; loads are
// coalesced across h. MLP=8 from the unroll hides L2 latency.
// ---------------------------------------------------------------------------
__global__ void __launch_bounds__(128) proto_proj_kernel(
    const float* __restrict__ protos,
    const float* __restrict__ W1,
    const float* __restrict__ b1)
{
    __shared__ float sp[4][EMBED];   // 16 KB

    const int pbase = blockIdx.x * 4;
    // cooperative load: 4*1024 floats = 1024 float4
    const float4* src = (const float4*)(protos + (size_t)pbase * EMBED);
    float4* dst = (float4*)&sp[0][0];
    #pragma unroll
    for (int i = 0; i < 8; i++)
        dst[threadIdx.x + 128 * i] = src[threadIdx.x + 128 * i];
    __syncthreads();

    const int h = threadIdx.x;
    float a0 = 0.f, a1 = 0.f, a2 = 0.f, a3 = 0.f;
    const float* w = W1 + (size_t)EMBED * HID + h;   // bottom half, column h

    for (int k = 0; k < EMBED; k += 8) {
        float wv[8];
        #pragma unroll
        for (int j = 0; j < 8; j++)
            wv[j] = w[(size_t)(k + j) * HID];        // 8 independent LDGs in flight
        #pragma unroll
        for (int j = 0; j < 8; j++) {
            a0 = fmaf(sp[0][k + j], wv[j], a0);
            a1 = fmaf(sp[1][k + j], wv[j], a1);
            a2 = fmaf(sp[2][k + j], wv[j], a2);
            a3 = fmaf(sp[3][k + j], wv[j], a3);
        }
    }
    const float bb = b1[h];
    g_pp[(pbase + 0) * HID + h] = a0 + bb;
    g_pp[(pbase + 1) * HID + h] = a1 + bb;
    g_pp[(pbase + 2) * HID + h] = a2 + bb;
    g_pp[(pbase + 3) * HID + h] = a3 + bb;
}

// ---------------------------------------------------------------------------
// Kernel 2: per-row argmin over 512 distances. One warp per query row.
// Tie-break to lowest index (matches jnp.argmin semantics).
// ---------------------------------------------------------------------------
__global__ void __launch_bounds__(256) argmin_kernel(const float* __restrict__ dist)
{
    int gwarp = (blockIdx.x * blockDim.x + threadIdx.x) >> 5;
    int lane  = threadIdx.x & 31;
    if (gwarp >= NQ) return;

    const float4* row = (const float4*)(dist + (size_t)gwarp * NPROTO);

    float best = __int_as_float(0x7f800000);   // +inf
    int   bi   = 0x7fffffff;
    #pragma unroll
    for (int j = 0; j < 4; j++) {
        int f4 = lane + 32 * j;                // ascending per lane -> earliest kept via strict <
        float4 v = row[f4];
        int base = f4 * 4;
        if (v.x < best) { best = v.x; bi = base;     }
        if (v.y < best) { best = v.y; bi = base + 1; }
        if (v.z < best) { best = v.z; bi = base + 2; }
        if (v.w < best) { best = v.w; bi = base + 3; }
    }
    #pragma unroll
    for (int off = 16; off; off >>= 1) {
        float ob = __shfl_down_sync(0xffffffffu, best, off);
        int   oi = __shfl_down_sync(0xffffffffu, bi,   off);
        if (ob < best || (ob == best && oi < bi)) { best = ob; bi = oi; }
    }
    if (lane == 0) g_idx[gwarp] = bi;
}

// ---------------------------------------------------------------------------
// Kernel 3: fused GEMM + epilogue (double-buffered smem, no forced reg cap).
//   h[m, :] = relu( qf[m, :] @ W1_top + g_pp[g_idx[m], :] )
//   out[m]  = sigmoid( h[m, :] @ W2 + b2 )
// Tile: BM=128, BN=128(full), BK=16. 256 threads (16x16), 8x8 microtile,
// accumulators as f32x2 pairs along N. A stored splatted in smem.
// Smem: 2 x (16x128 u64 + 16x128 f32) = 48 KB (static limit, exact).
// ---------------------------------------------------------------------------
#define KTILES (EMBED / 16)

__global__ void __launch_bounds__(256) mlp_kernel(
    const float* __restrict__ qf,
    const float* __restrict__ W1,
    const float* __restrict__ W2,
    const float* __restrict__ b2,
    float* __restrict__ out)
{
    __shared__ unsigned long long As[2][16][128];  // splatted (v,v), k-major; 32 KB
    __shared__ float Bs[2][16][128];               // 16 KB

    const int tid = threadIdx.x;
    const int tx  = tid & 15;    // N group (8 cols each)
    const int ty  = tid >> 4;    // M group (8 rows each)
    const int m0  = blockIdx.x * 128;

    unsigned long long acc[8][4];
    #pragma unroll
    for (int r = 0; r < 8; r++)
        #pragma unroll
        for (int c = 0; c < 4; c++) acc[r][c] = 0ull;   // (0.0f, 0.0f)

    // A load mapping: thread -> row arow, 8 consecutive k starting at kbase
    const int arow  = tid >> 1;
    const int kbase = (tid & 1) * 8;
    const float* aptr = qf + (size_t)(m0 + arow) * EMBED + kbase;

    // B load mapping: thread -> (row brow & brow+8, 4 cols at bcol)
    const int brow = tid >> 5;          // 0..7
    const int bcol = (tid & 31) * 4;
    const float* bptr = W1 + (size_t)brow * HID + bcol;

    // ---- prologue: load tile 0 into buffer 0 ----
    {
        float4 av0 = *(const float4*)(aptr);
        float4 av1 = *(const float4*)(aptr + 4);
        float4 bv0 = *(const float4*)(bptr);
        float4 bv1 = *(const float4*)(bptr + (size_t)8 * HID);

        As[0][kbase + 0][arow] = pack2(av0.x, av0.x);
        As[0][kbase + 1][arow] = pack2(av0.y, av0.y);
        As[0][kbase + 2][arow] = pack2(av0.z, av0.z);
        As[0][kbase + 3][arow] = pack2(av0.w, av0.w);
        As[0][kbase + 4][arow] = pack2(av1.x, av1.x);
        As[0][kbase + 5][arow] = pack2(av1.y, av1.y);
        As[0][kbase + 6][arow] = pack2(av1.z, av1.z);
        As[0][kbase + 7][arow] = pack2(av1.w, av1.w);
        *(float4*)&Bs[0][brow][bcol]     = bv0;
        *(float4*)&Bs[0][brow + 8][bcol] = bv1;
    }
    __syncthreads();

    for (int kt = 0; kt < KTILES; kt++) {
        const int cur = kt & 1;

        // ---- prefetch next tile's global loads (latency hidden by compute) ----
        float4 av0, av1, bv0, bv1;
        if (kt < KTILES - 1) {
            const int k1 = (kt + 1) * 16;
            av0 = *(const float4*)(aptr + k1);
            av1 = *(const float4*)(aptr + k1 + 4);
            bv0 = *(const float4*)(bptr + (size_t)k1 * HID);
            bv1 = *(const float4*)(bptr + (size_t)(k1 + 8) * HID);
        }

        // ---- compute on current buffer ----
        #pragma unroll
        for (int k = 0; k < 16; k++) {
            ulonglong2 a01 = *(const ulonglong2*)&As[cur][k][ty * 8 + 0];
            ulonglong2 a23 = *(const ulonglong2*)&As[cur][k][ty * 8 + 2];
            ulonglong2 a45 = *(const ulonglong2*)&As[cur][k][ty * 8 + 4];
            ulonglong2 a67 = *(const ulonglong2*)&As[cur][k][ty * 8 + 6];
            ulonglong2 b01 = *(const ulonglong2*)&Bs[cur][k][tx * 8 + 0];
            ulonglong2 b23 = *(const ulonglong2*)&Bs[cur][k][tx * 8 + 4];

            acc[0][0] = fma2(a01.x, b01.x, acc[0][0]);
            acc[0][1] = fma2(a01.x, b01.y, acc[0][1]);
            acc[0][2] = fma2(a01.x, b23.x, acc[0][2]);
            acc[0][3] = fma2(a01.x, b23.y, acc[0][3]);
            acc[1][0] = fma2(a01.y, b01.x, acc[1][0]);
            acc[1][1] = fma2(a01.y, b01.y, acc[1][1]);
            acc[1][2] = fma2(a01.y, b23.x, acc[1][2]);
            acc[1][3] = fma2(a01.y, b23.y, acc[1][3]);
            acc[2][0] = fma2(a23.x, b01.x, acc[2][0]);
            acc[2][1] = fma2(a23.x, b01.y, acc[2][1]);
            acc[2][2] = fma2(a23.x, b23.x, acc[2][2]);
            acc[2][3] = fma2(a23.x, b23.y, acc[2][3]);
            acc[3][0] = fma2(a23.y, b01.x, acc[3][0]);
            acc[3][1] = fma2(a23.y, b01.y, acc[3][1]);
            acc[3][2] = fma2(a23.y, b23.x, acc[3][2]);
            acc[3][3] = fma2(a23.y, b23.y, acc[3][3]);
            acc[4][0] = fma2(a45.x, b01.x, acc[4][0]);
            acc[4][1] = fma2(a45.x, b01.y, acc[4][1]);
            acc[4][2] = fma2(a45.x, b23.x, acc[4][2]);
            acc[4][3] = fma2(a45.x, b23.y, acc[4][3]);
            acc[5][0] = fma2(a45.y, b01.x, acc[5][0]);
            acc[5][1] = fma2(a45.y, b01.y, acc[5][1]);
            acc[5][2] = fma2(a45.y, b23.x, acc[5][2]);
            acc[5][3] = fma2(a45.y, b23.y, acc[5][3]);
            acc[6][0] = fma2(a67.x, b01.x, acc[6][0]);
            acc[6][1] = fma2(a67.x, b01.y, acc[6][1]);
            acc[6][2] = fma2(a67.x, b23.x, acc[6][2]);
            acc[6][3] = fma2(a67.x, b23.y, acc[6][3]);
            acc[7][0] = fma2(a67.y, b01.x, acc[7][0]);
            acc[7][1] = fma2(a67.y, b01.y, acc[7][1]);
            acc[7][2] = fma2(a67.y, b23.x, acc[7][2]);
            acc[7][3] = fma2(a67.y, b23.y, acc[7][3]);
        }

        // ---- stage next tile into the other buffer ----
        if (kt < KTILES - 1) {
            const int nxt = cur ^ 1;
            As[nxt][kbase + 0][arow] = pack2(av0.x, av0.x);
            As[nxt][kbase + 1][arow] = pack2(av0.y, av0.y);
            As[nxt][kbase + 2][arow] = pack2(av0.z, av0.z);
            As[nxt][kbase + 3][arow] = pack2(av0.w, av0.w);
            As[nxt][kbase + 4][arow] = pack2(av1.x, av1.x);
            As[nxt][kbase + 5][arow] = pack2(av1.y, av1.y);
            As[nxt][kbase + 6][arow] = pack2(av1.z, av1.z);
            As[nxt][kbase + 7][arow] = pack2(av1.w, av1.w);
            *(float4*)&Bs[nxt][brow][bcol]     = bv0;
            *(float4*)&Bs[nxt][brow + 8][bcol] = bv1;
        }
        __syncthreads();
    }

    // ---- fused epilogue: +pp[idx] (b1 folded), relu, dot with W2, sigmoid ----
    float w2v[8];
    #pragma unroll
    for (int c = 0; c < 8; c++) w2v[c] = W2[tx * 8 + c];
    const float bias2 = b2[0];

    #pragma unroll
    for (int r = 0; r < 8; r++) {
        const int m = m0 + ty * 8 + r;
        const int pidx = g_idx[m];
        const float* pp = g_pp + (size_t)pidx * HID + tx * 8;
        float4 p0 = *(const float4*)(pp);
        float4 p1 = *(const float4*)(pp + 4);
        float pa[8] = {p0.x, p0.y, p0.z, p0.w, p1.x, p1.y, p1.z, p1.w};

        float s = 0.f;
        #pragma unroll
        for (int c = 0; c < 4; c++) {
            float h0, h1;
            unpack2(h0, h1, acc[r][c]);
            float v0 = h0 + pa[2 * c];
            float v1 = h1 + pa[2 * c + 1];
            v0 = v0 > 0.f ? v0 : 0.f;
            v1 = v1 > 0.f ? v1 : 0.f;
            s = fmaf(v0, w2v[2 * c], s);
            s = fmaf(v1, w2v[2 * c + 1], s);
        }
        // reduce across the 16 tx lanes (same warp, width-16 segments)
        #pragma unroll
        for (int off = 8; off; off >>= 1)
            s += __shfl_down_sync(0xffffffffu, s, off, 16);

        if (tx == 0)
            out[m] = 1.0f / (1.0f + expf(-(s + bias2)));
    }
}

// ---------------------------------------------------------------------------
// Launch: proto_proj and argmin are independent; mlp consumes both.
// All plain launches on the capture stream; no allocs, no syncs.
// ---------------------------------------------------------------------------
extern "C" void kernel_launch(void* const* d_in, const int* in_sizes, int n_in,
                              void* d_out, int out_size)
{
    const float* qf     = (const float*)d_in[0];   // [65536,1024]
    const float* protos = (const float*)d_in[1];   // [512,1024]
    const float* dist   = (const float*)d_in[2];   // [65536,512]
    const float* W1     = (const float*)d_in[3];   // [2048,128]
    const float* b1     = (const float*)d_in[4];   // [128]
    const float* W2     = (const float*)d_in[5];   // [128]  (shape [128,1])
    const float* b2     = (const float*)d_in[6];   // [1]
    float* out = (float*)d_out;                    // [65536]

    proto_proj_kernel<<<NPROTO / 4, 128>>>(protos, W1, b1);
    argmin_kernel<<<(NQ * 32) / 256, 256>>>(dist);
    mlp_kernel<<<NQ / 128, 256>>>(qf, W1, W2, b2, out);
}